// round 1
// baseline (speedup 1.0000x reference)
#include <cuda_runtime.h>

#define D   128
#define D4  32
#define TR  32

static const int NMAX = 50000;
static const int EMAX = 400000;
static const int RMAX = 500;

typedef unsigned long long ull;

// ---------------- scratch (device globals; no runtime allocation) ----------------
__device__ float g_Se   [NMAX * D];   // edge layer: already W-transformed accumulation
__device__ float g_SinN [NMAX * D];
__device__ float g_SoutN[NMAX * D];
__device__ float g_SinC [NMAX * D];
__device__ float g_SoutC[NMAX * D];
__device__ float g_preN [NMAX * D];
__device__ float g_preC [NMAX * D];
__device__ float g_ew   [3][EMAX];     // logits, then exp values
__device__ int   g_mx   [3][NMAX];     // ordered-int encoded segment max
__device__ float g_ss   [3][NMAX];     // segment exp sums
__device__ float g_A    [4][NMAX];     // AinN, AoutN, AinC, AoutC
__device__ float g_WiRb [RMAX * D];    // edge_Wi @ rel + edge_bi
__device__ float g_WoRb [RMAX * D];
__device__ ull   g_WTP  [7][(D / 2) * D]; // packed-pair transposed weights
__device__ float g_bnsum[3][D];
__device__ float g_bnsq [3][D];
__device__ float g_mu   [3][D];
__device__ float g_rsig [3][D];
__device__ float g_relsum[RMAX * D];
__device__ float g_relcnt[RMAX];
__device__ unsigned char g_mask8[EMAX];
__device__ int   g_maskmode;

// ---------------- helpers ----------------
__device__ __forceinline__ ull pack2(float a, float b) {
    ull r; asm("mov.b64 %0,{%1,%2};" : "=l"(r) : "f"(a), "f"(b)); return r;
}
__device__ __forceinline__ void fma2(ull& d, ull a, ull b) {
    asm("fma.rn.f32x2 %0,%1,%2,%0;" : "+l"(d) : "l"(a), "l"(b));
}
__device__ __forceinline__ float2 unpack2(ull v) {
    float lo, hi; asm("mov.b64 {%0,%1},%2;" : "=f"(lo), "=f"(hi) : "l"(v));
    return make_float2(lo, hi);
}
__device__ __forceinline__ int fenc(float f) {
    int i = __float_as_int(f); return i >= 0 ? i : (i ^ 0x7fffffff);
}
__device__ __forceinline__ float fdec(int i) {
    return __int_as_float(i >= 0 ? i : (i ^ 0x7fffffff));
}

// ---------------- mask dtype detection + normalization ----------------
__global__ void k_detect(const int* m) {
    if (threadIdx.x == 0) {
        int allb = 1, allf = 1;
        for (int i = 0; i < 64; i++) {
            int w = m[i];
            if (w != 0 && w != 1) allb = 0;
            if (w != 0 && w != 0x3F800000) allf = 0;
        }
        g_maskmode = allb ? 0 : (allf ? 1 : 2);
    }
}
__global__ void k_masknorm(const void* m, int E) {
    int i = blockIdx.x * blockDim.x + threadIdx.x;
    if (i >= E) return;
    int mode = g_maskmode;
    unsigned char v;
    if (mode == 0)      v = ((const int*)m)[i] != 0;
    else if (mode == 1) v = ((const float*)m)[i] != 0.f;
    else                v = ((const unsigned char*)m)[i] != 0;
    g_mask8[i] = v;
}

// ---------------- zeroing ----------------
__global__ void k_zero_big() {
    int i = blockIdx.x * blockDim.x + threadIdx.x;
    int s = gridDim.x * blockDim.x;
    float4 z = make_float4(0.f, 0.f, 0.f, 0.f);
    int n4 = NMAX * D / 4;
    for (int j = i; j < n4; j += s) {
        ((float4*)g_Se)[j]    = z;
        ((float4*)g_SinN)[j]  = z;
        ((float4*)g_SoutN)[j] = z;
        ((float4*)g_SinC)[j]  = z;
        ((float4*)g_SoutC)[j] = z;
    }
}
__global__ void k_zero_small() {
    int i = blockIdx.x * blockDim.x + threadIdx.x;
    int s = gridDim.x * blockDim.x;
    for (int j = i; j < 3 * NMAX; j += s) { ((float*)g_ss)[j] = 0.f; ((int*)g_mx)[j] = (int)0x80000000; }
    for (int j = i; j < 4 * NMAX; j += s) ((float*)g_A)[j] = 0.f;
    for (int j = i; j < 3 * D;    j += s) { ((float*)g_bnsum)[j] = 0.f; ((float*)g_bnsq)[j] = 0.f; }
    for (int j = i; j < RMAX * D; j += s) g_relsum[j] = 0.f;
    for (int j = i; j < RMAX;     j += s) g_relcnt[j] = 0.f;
}

// ---------------- weight pre-pack: WTP[m][k2*D+c] = (W[c][2k2], W[c][2k2+1]) ----------------
__global__ void k_buildWTP(const float* w0, const float* w1, const float* w2, const float* w3,
                           const float* w4, const float* w5, const float* w6) {
    const float* ws[7] = {w0, w1, w2, w3, w4, w5, w6};
    int m = blockIdx.y, k2 = blockIdx.x, c = threadIdx.x;
    const float* W = ws[m];
    g_WTP[m][k2 * D + c] = pack2(W[c * D + 2 * k2], W[c * D + 2 * k2 + 1]);
}

// ---------------- WiRb / WoRb = edge_W{i,o} @ rel + b ----------------
__global__ void k_wrel(const float* rel, const float* bi, const float* bo) {
    int r = blockIdx.x, io = blockIdx.y, c = threadIdx.x;
    __shared__ __align__(16) float xs[D];
    xs[c] = rel[r * D + c];
    __syncthreads();
    const ull* WP = g_WTP[io];
    ull acc = 0ull;
#pragma unroll
    for (int k2 = 0; k2 < D / 2; k2++)
        fma2(acc, *(const ull*)&xs[2 * k2], WP[k2 * D + c]);
    float2 f = unpack2(acc);
    float v = f.x + f.y + (io ? bo[c] : bi[c]);
    (io ? g_WoRb : g_WiRb)[r * D + c] = v;
}

// ---------------- pass 1: logits + segment max (warp per edge) ----------------
__global__ void __launch_bounds__(256) k_pass1(const float4* ent, const float4* rel,
                                               const int* src, const int* dst, const int* et, int E) {
    int w = (blockIdx.x * blockDim.x + threadIdx.x) >> 5;
    if (w >= E) return;
    int lane = threadIdx.x & 31;
    int s = __ldg(&src[w]), d = __ldg(&dst[w]), r = __ldg(&et[w]);
    float4 sv = __ldg(&ent[s * D4 + lane]);
    float4 dv = __ldg(&ent[d * D4 + lane]);
    float4 rv = __ldg(&rel[r * D4 + lane]);
    float l0 = rv.x * dv.x + rv.y * dv.y + rv.z * dv.z + rv.w * dv.w;
    float l1 = sv.x * dv.x + sv.y * dv.y + sv.z * dv.z + sv.w * dv.w;
    float l2 = sv.x * rv.x * dv.x + sv.y * rv.y * dv.y + sv.z * rv.z * dv.z + sv.w * rv.w * dv.w;
#pragma unroll
    for (int o = 16; o; o >>= 1) {
        l0 += __shfl_xor_sync(0xffffffffu, l0, o);
        l1 += __shfl_xor_sync(0xffffffffu, l1, o);
        l2 += __shfl_xor_sync(0xffffffffu, l2, o);
    }
    if (lane == 0) {
        g_ew[0][w] = l0; g_ew[1][w] = l1; g_ew[2][w] = l2;
        atomicMax(&g_mx[0][d], fenc(l0));
        atomicMax(&g_mx[1][d], fenc(l1));
        atomicMax(&g_mx[2][d], fenc(l2));
    }
}

// ---------------- pass 2: exp + segment sum ----------------
__global__ void __launch_bounds__(256) k_pass2(const int* dst, int E) {
    int e = blockIdx.x * blockDim.x + threadIdx.x;
    if (e >= E) return;
    int d = __ldg(&dst[e]);
#pragma unroll
    for (int l = 0; l < 3; l++) {
        float v = __expf(g_ew[l][e] - fdec(g_mx[l][d]));
        g_ew[l][e] = v;
        atomicAdd(&g_ss[l][d], v);
    }
}

// ---------------- pass 3: weighted scatter-accumulate (warp per edge) ----------------
__global__ void __launch_bounds__(256) k_pass3(const float4* ent, const float4* rel,
                                               const int* src, const int* dst, const int* et, int E) {
    int w = (blockIdx.x * blockDim.x + threadIdx.x) >> 5;
    if (w >= E) return;
    int lane = threadIdx.x & 31;
    int s = __ldg(&src[w]), d = __ldg(&dst[w]), r = __ldg(&et[w]);
    bool in = g_mask8[w] != 0;
    float a0 = g_ew[0][w] / g_ss[0][d];
    float a1 = g_ew[1][w] / g_ss[1][d];
    float a2 = g_ew[2][w] / g_ss[2][d];
    float4 sv = __ldg(&ent[s * D4 + lane]);
    float4 rv = __ldg(&rel[r * D4 + lane]);
    const float4* T = in ? (const float4*)g_WiRb : (const float4*)g_WoRb;
    float4 tv = __ldg(&T[r * D4 + lane]);
    float* Sn = in ? g_SinN : g_SoutN;
    float* Sc = in ? g_SinC : g_SoutC;
    int base = d * D + lane * 4;
    atomicAdd(&g_Se[base + 0], a0 * tv.x);
    atomicAdd(&g_Se[base + 1], a0 * tv.y);
    atomicAdd(&g_Se[base + 2], a0 * tv.z);
    atomicAdd(&g_Se[base + 3], a0 * tv.w);
    atomicAdd(&Sn[base + 0], a1 * sv.x);
    atomicAdd(&Sn[base + 1], a1 * sv.y);
    atomicAdd(&Sn[base + 2], a1 * sv.z);
    atomicAdd(&Sn[base + 3], a1 * sv.w);
    atomicAdd(&Sc[base + 0], a2 * sv.x * rv.x);
    atomicAdd(&Sc[base + 1], a2 * sv.y * rv.y);
    atomicAdd(&Sc[base + 2], a2 * sv.z * rv.z);
    atomicAdd(&Sc[base + 3], a2 * sv.w * rv.w);
    if (lane == 0) {
        atomicAdd(&g_A[in ? 0 : 1][d], a1);
        atomicAdd(&g_A[in ? 2 : 3][d], a2);
    }
}

// ---------------- node/comp GEMMs: pre = Wi Sin + bi Ain + Wo Sout + bo Aout ----------------
__global__ void __launch_bounds__(128) k_gemm(const float* nbi, const float* nbo,
                                              const float* cbi, const float* cbo, int N) {
    int layer = blockIdx.y; // 0 node, 1 comp
    const float* Xin  = layer ? g_SinC  : g_SinN;
    const float* Xout = layer ? g_SoutC : g_SoutN;
    const ull* WPi = g_WTP[2 + 2 * layer];
    const ull* WPo = g_WTP[3 + 2 * layer];
    const float* Ain  = g_A[2 * layer];
    const float* Aout = g_A[2 * layer + 1];
    const float* bi = layer ? cbi : nbi;
    const float* bo = layer ? cbo : nbo;
    float* pre = layer ? g_preC : g_preN;

    __shared__ __align__(16) float xin_s[TR][D];
    __shared__ __align__(16) float xout_s[TR][D];
    __shared__ float ain_s[TR], aout_s[TR];
    int tid = threadIdx.x;
    int r0 = blockIdx.x * TR;
    for (int i = tid; i < TR * D4; i += 128) {
        int r = i >> 5, j = i & 31, gr = r0 + r;
        float4 z = make_float4(0.f, 0.f, 0.f, 0.f);
        float4 a = gr < N ? __ldg(&((const float4*)Xin)[gr * D4 + j])  : z;
        float4 b = gr < N ? __ldg(&((const float4*)Xout)[gr * D4 + j]) : z;
        ((float4*)xin_s[r])[j]  = a;
        ((float4*)xout_s[r])[j] = b;
    }
    if (tid < TR) {
        int gr = r0 + tid;
        ain_s[tid]  = gr < N ? Ain[gr]  : 0.f;
        aout_s[tid] = gr < N ? Aout[gr] : 0.f;
    }
    __syncthreads();
    int c = tid;
    ull acc[TR];
#pragma unroll
    for (int r = 0; r < TR; r++) acc[r] = 0ull;
    for (int k = 0; k < D; k += 4) {
        int k2 = k >> 1;
        ull wiA = WPi[k2 * D + c], wiB = WPi[(k2 + 1) * D + c];
        ull woA = WPo[k2 * D + c], woB = WPo[(k2 + 1) * D + c];
#pragma unroll
        for (int r = 0; r < TR; r++) {
            ulonglong2 xi = *(const ulonglong2*)&xin_s[r][k];
            ulonglong2 xo = *(const ulonglong2*)&xout_s[r][k];
            fma2(acc[r], xi.x, wiA); fma2(acc[r], xi.y, wiB);
            fma2(acc[r], xo.x, woA); fma2(acc[r], xo.y, woB);
        }
    }
    float bic = bi[c], boc = bo[c];
    float s = 0.f, q = 0.f;
#pragma unroll
    for (int r = 0; r < TR; r++) {
        int gr = r0 + r;
        float2 f = unpack2(acc[r]);
        float v = f.x + f.y + ain_s[r] * bic + aout_s[r] * boc;
        if (gr < N) { pre[gr * D + c] = v; s += v; q += v * v; }
    }
    atomicAdd(&g_bnsum[1 + layer][c], s);
    atomicAdd(&g_bnsq[1 + layer][c], q);
}

// ---------------- BN stats for edge layer (pre_e == g_Se) ----------------
__global__ void k_bnstat0(int N) {
    int c = threadIdx.x;
    float s = 0.f, q = 0.f;
    for (int row = blockIdx.x; row < N; row += gridDim.x) {
        float v = g_Se[row * D + c];
        s += v; q += v * v;
    }
    atomicAdd(&g_bnsum[0][c], s);
    atomicAdd(&g_bnsq[0][c], q);
}
__global__ void k_bnfin(int N) {
    int t = threadIdx.x;
    if (t >= 3 * D) return;
    int l = t >> 7, c = t & 127;
    float invN = 1.f / (float)N;
    float mu = g_bnsum[l][c] * invN;
    float var = g_bnsq[l][c] * invN - mu * mu;
    g_mu[l][c] = mu;
    g_rsig[l][c] = rsqrtf(var + 1e-5f);
}

// ---------------- final entity output ----------------
__global__ void __launch_bounds__(256) k_final(const float* ent,
                                               const float* ge, const float* be,
                                               const float* gn, const float* bn,
                                               const float* gc, const float* bc,
                                               float* out, int n) {
    int i = blockIdx.x * blockDim.x + threadIdx.x;
    if (i >= n) return;
    int c = i & 127;
    float x0 = (g_Se[i]   - g_mu[0][c]) * g_rsig[0][c];
    float x1 = (g_preN[i] - g_mu[1][c]) * g_rsig[1][c];
    float x2 = (g_preC[i] - g_mu[2][c]) * g_rsig[2][c];
    out[i] = ent[i] + tanhf(fmaf(ge[c], x0, be[c]))
                    + tanhf(fmaf(gn[c], x1, bn[c]))
                    + tanhf(fmaf(gc[c], x2, bc[c]));
}

// ---------------- relation update ----------------
__global__ void __launch_bounds__(256) k_rel1(const float4* ent, const int* heads,
                                              const int* tails, const int* rid, int P) {
    int p = (blockIdx.x * blockDim.x + threadIdx.x) >> 5;
    if (p >= P) return;
    int lane = threadIdx.x & 31;
    int h = __ldg(&heads[p]), t = __ldg(&tails[p]), r = __ldg(&rid[p]);
    float4 tv = __ldg(&ent[t * D4 + lane]);
    float4 hv = __ldg(&ent[h * D4 + lane]);
    int base = r * D + lane * 4;
    atomicAdd(&g_relsum[base + 0], tv.x - hv.x);
    atomicAdd(&g_relsum[base + 1], tv.y - hv.y);
    atomicAdd(&g_relsum[base + 2], tv.z - hv.z);
    atomicAdd(&g_relsum[base + 3], tv.w - hv.w);
    if (lane == 0) atomicAdd(&g_relcnt[r], 1.f);
}
__global__ void k_rel2(const float* rel, const float* relb, float* out) {
    int r = blockIdx.x, c = threadIdx.x;
    __shared__ __align__(16) float xs[D];
    float cnt = fmaxf(g_relcnt[r], 1.f);
    xs[c] = g_relsum[r * D + c] / cnt;
    __syncthreads();
    const ull* WP = g_WTP[6];
    ull acc = 0ull;
#pragma unroll
    for (int k2 = 0; k2 < D / 2; k2++)
        fma2(acc, *(const ull*)&xs[2 * k2], WP[k2 * D + c]);
    float2 f = unpack2(acc);
    out[r * D + c] = rel[r * D + c] + tanhf(f.x + f.y + relb[c]);
}

// ---------------- launcher ----------------
extern "C" void kernel_launch(void* const* d_in, const int* in_sizes, int n_in,
                              void* d_out, int out_size) {
    const float* ent = (const float*)d_in[0];
    const float* rel = (const float*)d_in[1];
    const float* eWo = (const float*)d_in[2];  const float* ebo = (const float*)d_in[3];
    const float* eWi = (const float*)d_in[4];  const float* ebi = (const float*)d_in[5];
    const float* eg  = (const float*)d_in[6];  const float* eb  = (const float*)d_in[7];
    const float* nWo = (const float*)d_in[8];  const float* nbo = (const float*)d_in[9];
    const float* nWi = (const float*)d_in[10]; const float* nbi = (const float*)d_in[11];
    const float* ng  = (const float*)d_in[12]; const float* nb  = (const float*)d_in[13];
    const float* cWo = (const float*)d_in[14]; const float* cbo = (const float*)d_in[15];
    const float* cWi = (const float*)d_in[16]; const float* cbi = (const float*)d_in[17];
    const float* cg  = (const float*)d_in[18]; const float* cb  = (const float*)d_in[19];
    const float* rW  = (const float*)d_in[20]; const float* rb  = (const float*)d_in[21];
    const int* src = (const int*)d_in[22];
    const int* dst = (const int*)d_in[23];
    const int* et  = (const int*)d_in[24];

    // Resolve input ordering ambiguity (reference-signature order vs setup-dict order)
    int iIn, iH, iT, iR;
    if (in_sizes[25] == in_sizes[22]) { iIn = 25; iH = 27; iT = 28; iR = 29; }
    else                              { iH = 25;  iT = 26; iR = 27; iIn = 28; }
    const void* maskp = d_in[iIn];
    const int* heads = (const int*)d_in[iH];
    const int* tails = (const int*)d_in[iT];
    const int* rid   = (const int*)d_in[iR];

    int N = in_sizes[0] / D;
    int R = in_sizes[1] / D;
    int E = in_sizes[22];
    int P = in_sizes[iH];
    if (N > NMAX) N = NMAX;
    if (E > EMAX) E = EMAX;
    if (R > RMAX) R = RMAX;

    k_detect<<<1, 32>>>((const int*)maskp);
    k_masknorm<<<(E + 255) / 256, 256>>>(maskp, E);
    k_zero_big<<<1024, 256>>>();
    k_zero_small<<<256, 256>>>();
    k_buildWTP<<<dim3(64, 7), 128>>>(eWi, eWo, nWi, nWo, cWi, cWo, rW);
    k_wrel<<<dim3(R, 2), 128>>>(rel, ebi, ebo);
    k_pass1<<<(E * 32 + 255) / 256, 256>>>((const float4*)ent, (const float4*)rel, src, dst, et, E);
    k_pass2<<<(E + 255) / 256, 256>>>(dst, E);
    k_pass3<<<(E * 32 + 255) / 256, 256>>>((const float4*)ent, (const float4*)rel, src, dst, et, E);
    k_gemm<<<dim3((N + TR - 1) / TR, 2), 128>>>(nbi, nbo, cbi, cbo, N);
    k_bnstat0<<<512, 128>>>(N);
    k_bnfin<<<1, 384>>>(N);
    k_final<<<(N * D + 255) / 256, 256>>>(ent, eg, eb, ng, nb, cg, cb, (float*)d_out, N * D);
    if (out_size >= N * D + R * D) {
        k_rel1<<<(P * 32 + 255) / 256, 256>>>((const float4*)ent, heads, tails, rid, P);
        k_rel2<<<R, 128>>>(rel, rb, (float*)d_out + N * D);
    }
}

// round 2
// speedup vs baseline: 1.5902x; 1.5902x over previous
#include <cuda_runtime.h>

#define D   128
#define D4  32
#define TR  32

static const int NMAX = 50000;
static const int EMAX = 400000;
static const int RMAX = 500;

typedef unsigned long long ull;

// ---------------- scratch (device globals; no runtime allocation) ----------------
__device__ float g_Se   [NMAX * D];
__device__ float g_SinN [NMAX * D];
__device__ float g_SoutN[NMAX * D];
__device__ float g_SinC [NMAX * D];
__device__ float g_SoutC[NMAX * D];
__device__ float g_preN [NMAX * D];
__device__ float g_preC [NMAX * D];
__device__ float g_A    [4][NMAX];
__device__ float g_WiRb [RMAX * D];
__device__ float g_WoRb [RMAX * D];
__device__ ull   g_WTP  [7][(D / 2) * D];
__device__ float g_bnsum[3][D];
__device__ float g_bnsq [3][D];
__device__ float g_mu   [3][D];
__device__ float g_rsig [3][D];
__device__ float g_relsum[RMAX * D];
__device__ float g_relcnt[RMAX];
__device__ unsigned char g_mask8[EMAX];
__device__ int   g_maskmode;
__device__ int   g_cnt [NMAX];
__device__ int   g_off [NMAX];
__device__ int   g_cur [NMAX];
__device__ int   g_perm[EMAX];
__device__ int   g_bsum[256];

// ---------------- helpers ----------------
__device__ __forceinline__ ull pack2(float a, float b) {
    ull r; asm("mov.b64 %0,{%1,%2};" : "=l"(r) : "f"(a), "f"(b)); return r;
}
__device__ __forceinline__ void fma2(ull& d, ull a, ull b) {
    asm("fma.rn.f32x2 %0,%1,%2,%0;" : "+l"(d) : "l"(a), "l"(b));
}
__device__ __forceinline__ float2 unpack2(ull v) {
    float lo, hi; asm("mov.b64 {%0,%1},%2;" : "=f"(lo), "=f"(hi) : "l"(v));
    return make_float2(lo, hi);
}

// ---------------- mask dtype detection + normalization ----------------
__global__ void k_detect(const int* m) {
    if (threadIdx.x == 0) {
        int allb = 1, allf = 1;
        for (int i = 0; i < 64; i++) {
            int w = m[i];
            if (w != 0 && w != 1) allb = 0;
            if (w != 0 && w != 0x3F800000) allf = 0;
        }
        g_maskmode = allb ? 0 : (allf ? 1 : 2);
    }
}
__global__ void k_masknorm(const void* m, int E) {
    int i = blockIdx.x * blockDim.x + threadIdx.x;
    if (i >= E) return;
    int mode = g_maskmode;
    unsigned char v;
    if (mode == 0)      v = ((const int*)m)[i] != 0;
    else if (mode == 1) v = ((const float*)m)[i] != 0.f;
    else                v = ((const unsigned char*)m)[i] != 0;
    g_mask8[i] = v;
}

// ---------------- zeroing (small only; big arrays now written densely) ----------------
__global__ void k_zero_small() {
    int i = blockIdx.x * blockDim.x + threadIdx.x;
    int s = gridDim.x * blockDim.x;
    for (int j = i; j < NMAX;     j += s) g_cnt[j] = 0;
    for (int j = i; j < 3 * D;    j += s) { ((float*)g_bnsum)[j] = 0.f; ((float*)g_bnsq)[j] = 0.f; }
    for (int j = i; j < RMAX * D; j += s) g_relsum[j] = 0.f;
    for (int j = i; j < RMAX;     j += s) g_relcnt[j] = 0.f;
}

// ---------------- counting sort of edges by dst ----------------
__global__ void k_hist(const int* dst, int E) {
    int e = blockIdx.x * blockDim.x + threadIdx.x;
    if (e < E) atomicAdd(&g_cnt[dst[e]], 1);
}
__global__ void k_scanA(int N) {
    __shared__ int sh[256];
    int t = threadIdx.x, i = blockIdx.x * 256 + t;
    sh[t] = i < N ? g_cnt[i] : 0;
    __syncthreads();
    for (int o = 128; o; o >>= 1) { if (t < o) sh[t] += sh[t + o]; __syncthreads(); }
    if (t == 0) g_bsum[blockIdx.x] = sh[0];
}
__global__ void k_scanB(int nb) {
    __shared__ int sh[256];
    int t = threadIdx.x;
    int v = t < nb ? g_bsum[t] : 0;
    sh[t] = v; __syncthreads();
    for (int o = 1; o < 256; o <<= 1) {
        int u = t >= o ? sh[t - o] : 0;
        __syncthreads(); sh[t] += u; __syncthreads();
    }
    if (t < nb) g_bsum[t] = sh[t] - v;
}
__global__ void k_scanC(int N) {
    __shared__ int sh[256];
    int t = threadIdx.x, i = blockIdx.x * 256 + t;
    int v = i < N ? g_cnt[i] : 0;
    sh[t] = v; __syncthreads();
    for (int o = 1; o < 256; o <<= 1) {
        int u = t >= o ? sh[t - o] : 0;
        __syncthreads(); sh[t] += u; __syncthreads();
    }
    if (i < N) {
        int off = g_bsum[blockIdx.x] + sh[t] - v;
        g_off[i] = off; g_cur[i] = off;
    }
}
__global__ void k_scatter(const int* dst, int E) {
    int e = blockIdx.x * blockDim.x + threadIdx.x;
    if (e >= E) return;
    int p = atomicAdd(&g_cur[dst[e]], 1);
    g_perm[p] = e;
}

// ---------------- weight pre-pack ----------------
__global__ void k_buildWTP(const float* w0, const float* w1, const float* w2, const float* w3,
                           const float* w4, const float* w5, const float* w6) {
    const float* ws[7] = {w0, w1, w2, w3, w4, w5, w6};
    int m = blockIdx.y, k2 = blockIdx.x, c = threadIdx.x;
    const float* W = ws[m];
    g_WTP[m][k2 * D + c] = pack2(W[c * D + 2 * k2], W[c * D + 2 * k2 + 1]);
}

// ---------------- WiRb / WoRb = edge_W{i,o} @ rel + b ----------------
__global__ void k_wrel(const float* rel, const float* bi, const float* bo) {
    int r = blockIdx.x, io = blockIdx.y, c = threadIdx.x;
    __shared__ __align__(16) float xs[D];
    xs[c] = rel[r * D + c];
    __syncthreads();
    const ull* WP = g_WTP[io];
    ull acc = 0ull;
#pragma unroll
    for (int k2 = 0; k2 < D / 2; k2++)
        fma2(acc, *(const ull*)&xs[2 * k2], WP[k2 * D + c]);
    float2 f = unpack2(acc);
    float v = f.x + f.y + (io ? bo[c] : bi[c]);
    (io ? g_WoRb : g_WiRb)[r * D + c] = v;
}

// ---------------- fused per-dst online-softmax aggregation (warp per node) ----------------
__global__ void __launch_bounds__(256) k_fused(const float4* ent, const float4* rel,
                                               const int* src, const int* et, int N) {
    int n = (blockIdx.x * blockDim.x + threadIdx.x) >> 5;
    if (n >= N) return;
    int lane = threadIdx.x & 31;
    int start = g_off[n], cnt = g_cnt[n];
    int base = n * D4 + lane;
    float4 z = make_float4(0.f, 0.f, 0.f, 0.f);
    if (cnt == 0) {
        ((float4*)g_Se)[base] = z; ((float4*)g_SinN)[base] = z; ((float4*)g_SoutN)[base] = z;
        ((float4*)g_SinC)[base] = z; ((float4*)g_SoutC)[base] = z;
        if (lane == 0) { g_A[0][n] = 0.f; g_A[1][n] = 0.f; g_A[2][n] = 0.f; g_A[3][n] = 0.f; }
        return;
    }
    float4 dv = __ldg(&ent[base]);
    const float NEG = -1e30f;
    float m0 = NEG, m1 = NEG, m2 = NEG;
    float s0 = 0.f, s1i = 0.f, s1o = 0.f, s2i = 0.f, s2o = 0.f;
    float4 a0 = z, a1 = z, a2 = z, a3 = z, a4 = z;

    for (int j0 = 0; j0 < cnt; j0 += 32) {
        int mys = 0, myr = 0, myin = 0;
        int idx = j0 + lane;
        if (idx < cnt) {
            int e = __ldg(&g_perm[start + idx]);
            mys = __ldg(&src[e]); myr = __ldg(&et[e]); myin = g_mask8[e];
        }
        int lim = min(32, cnt - j0);
        for (int j = 0; j < lim; j++) {
            int s  = __shfl_sync(0xffffffffu, mys,  j);
            int r  = __shfl_sync(0xffffffffu, myr,  j);
            int in = __shfl_sync(0xffffffffu, myin, j);
            float4 sv = __ldg(&ent[s * D4 + lane]);
            float4 rv = __ldg(&rel[r * D4 + lane]);
            const float4* T = in ? (const float4*)g_WiRb : (const float4*)g_WoRb;
            float4 tv = __ldg(&T[r * D4 + lane]);
            float4 cv = make_float4(sv.x * rv.x, sv.y * rv.y, sv.z * rv.z, sv.w * rv.w);
            float p0 = rv.x * dv.x + rv.y * dv.y + rv.z * dv.z + rv.w * dv.w;
            float p1 = sv.x * dv.x + sv.y * dv.y + sv.z * dv.z + sv.w * dv.w;
            float p2 = cv.x * dv.x + cv.y * dv.y + cv.z * dv.z + cv.w * dv.w;
#pragma unroll
            for (int o = 16; o; o >>= 1) {
                p0 += __shfl_xor_sync(0xffffffffu, p0, o);
                p1 += __shfl_xor_sync(0xffffffffu, p1, o);
                p2 += __shfl_xor_sync(0xffffffffu, p2, o);
            }
            float nm = fmaxf(m0, p0);
            float sc = __expf(m0 - nm), w = __expf(p0 - nm); m0 = nm;
            s0 = s0 * sc + w;
            a0.x = a0.x * sc + w * tv.x; a0.y = a0.y * sc + w * tv.y;
            a0.z = a0.z * sc + w * tv.z; a0.w = a0.w * sc + w * tv.w;

            nm = fmaxf(m1, p1);
            sc = __expf(m1 - nm); w = __expf(p1 - nm); m1 = nm;
            s1i *= sc; s1o *= sc;
            a1.x *= sc; a1.y *= sc; a1.z *= sc; a1.w *= sc;
            a2.x *= sc; a2.y *= sc; a2.z *= sc; a2.w *= sc;
            if (in) { s1i += w; a1.x += w * sv.x; a1.y += w * sv.y; a1.z += w * sv.z; a1.w += w * sv.w; }
            else    { s1o += w; a2.x += w * sv.x; a2.y += w * sv.y; a2.z += w * sv.z; a2.w += w * sv.w; }

            nm = fmaxf(m2, p2);
            sc = __expf(m2 - nm); w = __expf(p2 - nm); m2 = nm;
            s2i *= sc; s2o *= sc;
            a3.x *= sc; a3.y *= sc; a3.z *= sc; a3.w *= sc;
            a4.x *= sc; a4.y *= sc; a4.z *= sc; a4.w *= sc;
            if (in) { s2i += w; a3.x += w * cv.x; a3.y += w * cv.y; a3.z += w * cv.z; a3.w += w * cv.w; }
            else    { s2o += w; a4.x += w * cv.x; a4.y += w * cv.y; a4.z += w * cv.z; a4.w += w * cv.w; }
        }
    }
    float r0 = 1.f / s0;
    float s1 = s1i + s1o, r1 = 1.f / s1;
    float s2 = s2i + s2o, r2 = 1.f / s2;
    ((float4*)g_Se)[base]    = make_float4(a0.x * r0, a0.y * r0, a0.z * r0, a0.w * r0);
    ((float4*)g_SinN)[base]  = make_float4(a1.x * r1, a1.y * r1, a1.z * r1, a1.w * r1);
    ((float4*)g_SoutN)[base] = make_float4(a2.x * r1, a2.y * r1, a2.z * r1, a2.w * r1);
    ((float4*)g_SinC)[base]  = make_float4(a3.x * r2, a3.y * r2, a3.z * r2, a3.w * r2);
    ((float4*)g_SoutC)[base] = make_float4(a4.x * r2, a4.y * r2, a4.z * r2, a4.w * r2);
    if (lane == 0) {
        g_A[0][n] = s1i * r1; g_A[1][n] = s1o * r1;
        g_A[2][n] = s2i * r2; g_A[3][n] = s2o * r2;
    }
}

// ---------------- node/comp GEMMs ----------------
__global__ void __launch_bounds__(128) k_gemm(const float* nbi, const float* nbo,
                                              const float* cbi, const float* cbo, int N) {
    int layer = blockIdx.y;
    const float* Xin  = layer ? g_SinC  : g_SinN;
    const float* Xout = layer ? g_SoutC : g_SoutN;
    const ull* WPi = g_WTP[2 + 2 * layer];
    const ull* WPo = g_WTP[3 + 2 * layer];
    const float* Ain  = g_A[2 * layer];
    const float* Aout = g_A[2 * layer + 1];
    const float* bi = layer ? cbi : nbi;
    const float* bo = layer ? cbo : nbo;
    float* pre = layer ? g_preC : g_preN;

    __shared__ __align__(16) float xin_s[TR][D];
    __shared__ __align__(16) float xout_s[TR][D];
    __shared__ float ain_s[TR], aout_s[TR];
    int tid = threadIdx.x;
    int r0 = blockIdx.x * TR;
    for (int i = tid; i < TR * D4; i += 128) {
        int r = i >> 5, j = i & 31, gr = r0 + r;
        float4 z = make_float4(0.f, 0.f, 0.f, 0.f);
        float4 a = gr < N ? __ldg(&((const float4*)Xin)[gr * D4 + j])  : z;
        float4 b = gr < N ? __ldg(&((const float4*)Xout)[gr * D4 + j]) : z;
        ((float4*)xin_s[r])[j]  = a;
        ((float4*)xout_s[r])[j] = b;
    }
    if (tid < TR) {
        int gr = r0 + tid;
        ain_s[tid]  = gr < N ? Ain[gr]  : 0.f;
        aout_s[tid] = gr < N ? Aout[gr] : 0.f;
    }
    __syncthreads();
    int c = tid;
    ull acc[TR];
#pragma unroll
    for (int r = 0; r < TR; r++) acc[r] = 0ull;
    for (int k = 0; k < D; k += 4) {
        int k2 = k >> 1;
        ull wiA = WPi[k2 * D + c], wiB = WPi[(k2 + 1) * D + c];
        ull woA = WPo[k2 * D + c], woB = WPo[(k2 + 1) * D + c];
#pragma unroll
        for (int r = 0; r < TR; r++) {
            ulonglong2 xi = *(const ulonglong2*)&xin_s[r][k];
            ulonglong2 xo = *(const ulonglong2*)&xout_s[r][k];
            fma2(acc[r], xi.x, wiA); fma2(acc[r], xi.y, wiB);
            fma2(acc[r], xo.x, woA); fma2(acc[r], xo.y, woB);
        }
    }
    float bic = bi[c], boc = bo[c];
    float s = 0.f, q = 0.f;
#pragma unroll
    for (int r = 0; r < TR; r++) {
        int gr = r0 + r;
        float2 f = unpack2(acc[r]);
        float v = f.x + f.y + ain_s[r] * bic + aout_s[r] * boc;
        if (gr < N) { pre[gr * D + c] = v; s += v; q += v * v; }
    }
    atomicAdd(&g_bnsum[1 + layer][c], s);
    atomicAdd(&g_bnsq[1 + layer][c], q);
}

// ---------------- BN stats ----------------
__global__ void k_bnstat0(int N) {
    int c = threadIdx.x;
    float s = 0.f, q = 0.f;
    for (int row = blockIdx.x; row < N; row += gridDim.x) {
        float v = g_Se[row * D + c];
        s += v; q += v * v;
    }
    atomicAdd(&g_bnsum[0][c], s);
    atomicAdd(&g_bnsq[0][c], q);
}
__global__ void k_bnfin(int N) {
    int t = threadIdx.x;
    if (t >= 3 * D) return;
    int l = t >> 7, c = t & 127;
    float invN = 1.f / (float)N;
    float mu = g_bnsum[l][c] * invN;
    float var = g_bnsq[l][c] * invN - mu * mu;
    g_mu[l][c] = mu;
    g_rsig[l][c] = rsqrtf(var + 1e-5f);
}

// ---------------- final entity output ----------------
__global__ void __launch_bounds__(256) k_final(const float* ent,
                                               const float* ge, const float* be,
                                               const float* gn, const float* bn,
                                               const float* gc, const float* bc,
                                               float* out, int n) {
    int i = blockIdx.x * blockDim.x + threadIdx.x;
    if (i >= n) return;
    int c = i & 127;
    float x0 = (g_Se[i]   - g_mu[0][c]) * g_rsig[0][c];
    float x1 = (g_preN[i] - g_mu[1][c]) * g_rsig[1][c];
    float x2 = (g_preC[i] - g_mu[2][c]) * g_rsig[2][c];
    out[i] = ent[i] + tanhf(fmaf(ge[c], x0, be[c]))
                    + tanhf(fmaf(gn[c], x1, bn[c]))
                    + tanhf(fmaf(gc[c], x2, bc[c]));
}

// ---------------- relation update ----------------
__global__ void __launch_bounds__(256) k_rel1(const float4* ent, const int* heads,
                                              const int* tails, const int* rid, int P) {
    int p = (blockIdx.x * blockDim.x + threadIdx.x) >> 5;
    if (p >= P) return;
    int lane = threadIdx.x & 31;
    int h = __ldg(&heads[p]), t = __ldg(&tails[p]), r = __ldg(&rid[p]);
    float4 tv = __ldg(&ent[t * D4 + lane]);
    float4 hv = __ldg(&ent[h * D4 + lane]);
    int base = r * D + lane * 4;
    atomicAdd(&g_relsum[base + 0], tv.x - hv.x);
    atomicAdd(&g_relsum[base + 1], tv.y - hv.y);
    atomicAdd(&g_relsum[base + 2], tv.z - hv.z);
    atomicAdd(&g_relsum[base + 3], tv.w - hv.w);
    if (lane == 0) atomicAdd(&g_relcnt[r], 1.f);
}
__global__ void k_rel2(const float* rel, const float* relb, float* out) {
    int r = blockIdx.x, c = threadIdx.x;
    __shared__ __align__(16) float xs[D];
    float cnt = fmaxf(g_relcnt[r], 1.f);
    xs[c] = g_relsum[r * D + c] / cnt;
    __syncthreads();
    const ull* WP = g_WTP[6];
    ull acc = 0ull;
#pragma unroll
    for (int k2 = 0; k2 < D / 2; k2++)
        fma2(acc, *(const ull*)&xs[2 * k2], WP[k2 * D + c]);
    float2 f = unpack2(acc);
    out[r * D + c] = rel[r * D + c] + tanhf(f.x + f.y + relb[c]);
}

// ---------------- launcher ----------------
extern "C" void kernel_launch(void* const* d_in, const int* in_sizes, int n_in,
                              void* d_out, int out_size) {
    const float* ent = (const float*)d_in[0];
    const float* rel = (const float*)d_in[1];
    const float* eWo = (const float*)d_in[2];  const float* ebo = (const float*)d_in[3];
    const float* eWi = (const float*)d_in[4];  const float* ebi = (const float*)d_in[5];
    const float* eg  = (const float*)d_in[6];  const float* eb  = (const float*)d_in[7];
    const float* nWo = (const float*)d_in[8];  const float* nbo = (const float*)d_in[9];
    const float* nWi = (const float*)d_in[10]; const float* nbi = (const float*)d_in[11];
    const float* ng  = (const float*)d_in[12]; const float* nbv = (const float*)d_in[13];
    const float* cWo = (const float*)d_in[14]; const float* cbo = (const float*)d_in[15];
    const float* cWi = (const float*)d_in[16]; const float* cbi = (const float*)d_in[17];
    const float* cg  = (const float*)d_in[18]; const float* cb  = (const float*)d_in[19];
    const float* rW  = (const float*)d_in[20]; const float* rb  = (const float*)d_in[21];
    const int* src = (const int*)d_in[22];
    const int* dst = (const int*)d_in[23];
    const int* et  = (const int*)d_in[24];

    int iIn, iH, iT, iR;
    if (in_sizes[25] == in_sizes[22]) { iIn = 25; iH = 27; iT = 28; iR = 29; }
    else                              { iH = 25;  iT = 26; iR = 27; iIn = 28; }
    const void* maskp = d_in[iIn];
    const int* heads = (const int*)d_in[iH];
    const int* tails = (const int*)d_in[iT];
    const int* rid   = (const int*)d_in[iR];

    int N = in_sizes[0] / D;
    int R = in_sizes[1] / D;
    int E = in_sizes[22];
    int P = in_sizes[iH];
    if (N > NMAX) N = NMAX;
    if (E > EMAX) E = EMAX;
    if (R > RMAX) R = RMAX;

    int nblk = (N + 255) / 256;

    k_detect<<<1, 32>>>((const int*)maskp);
    k_masknorm<<<(E + 255) / 256, 256>>>(maskp, E);
    k_zero_small<<<256, 256>>>();
    k_buildWTP<<<dim3(64, 7), 128>>>(eWi, eWo, nWi, nWo, cWi, cWo, rW);
    k_wrel<<<dim3(R, 2), 128>>>(rel, ebi, ebo);
    k_hist<<<(E + 255) / 256, 256>>>(dst, E);
    k_scanA<<<nblk, 256>>>(N);
    k_scanB<<<1, 256>>>(nblk);
    k_scanC<<<nblk, 256>>>(N);
    k_scatter<<<(E + 255) / 256, 256>>>(dst, E);
    k_fused<<<(N * 32 + 255) / 256, 256>>>((const float4*)ent, (const float4*)rel, src, et, N);
    k_gemm<<<dim3((N + TR - 1) / TR, 2), 128>>>(nbi, nbo, cbi, cbo, N);
    k_bnstat0<<<512, 128>>>(N);
    k_bnfin<<<1, 384>>>(N);
    k_final<<<(N * D + 255) / 256, 256>>>(ent, eg, eb, ng, nbv, cg, cb, (float*)d_out, N * D);
    if (out_size >= N * D + R * D) {
        k_rel1<<<(P * 32 + 255) / 256, 256>>>((const float4*)ent, heads, tails, rid, P);
        k_rel2<<<R, 128>>>(rel, rb, (float*)d_out + N * D);
    }
}